// round 15
// baseline (speedup 1.0000x reference)
#include <cuda_runtime.h>

#define NB 32
#define S 64
#define S2 (S*S)
#define S3 (S*S*S)
#define NPTS 65536
#define GRID_ELEMS (NB*S3)

__device__ float g_vox[GRID_ELEMS];   // f32 scatter target; re-zeroed by k_convz
__device__ float g_tmp[GRID_ELEMS];   // convXY output, layout [b][y][z][x]

// ---------------------------------------------------------------------------
// 21-tap Gaussian (sigma=3) as IEEE-754 immediates -> FFMA-imm (rt_SMSP=1).
// W0..W10 hex, symmetric. Values match the previously-validated decimals.
// ---------------------------------------------------------------------------
#define FMAW(HEX, acc, v) \
    asm("fma.rn.f32 %0, %1, 0f" HEX ", %0;" : "+f"(acc) : "f"(v))

#define TAPS(o, J) do {                                                  \
    FMAW("3A06D334", o, win[(J)+0]);   /* 5.143166e-04 */                \
    FMAW("3AC1B722", o, win[(J)+1]);   /* 1.477931e-03 */                \
    FMAW("3B790EE0", o, win[(J)+2]);   /* 3.800325e-03 */                \
    FMAW("3C0F4500", o, win[(J)+3]);   /* 8.744478e-03 */                \
    FMAW("3C937EED", o, win[(J)+4]);   /* 1.800486e-02 */                \
    FMAW("3D07E108", o, win[(J)+5]);   /* 3.317359e-02 */                \
    FMAW("3D6006BB", o, win[(J)+6]);   /* 5.469392e-02 */                \
    FMAW("3DA541FF", o, win[(J)+7]);   /* 8.069228e-02 */                \
    FMAW("3DDA2C09", o, win[(J)+8]);   /* 1.065293e-01 */                \
    FMAW("3E00DEAA", o, win[(J)+9]);   /* 1.258494e-01 */                \
    FMAW("3E083B6E", o, win[(J)+10]);  /* 1.330392e-01 */                \
    FMAW("3E00DEAA", o, win[(J)+11]);                                    \
    FMAW("3DDA2C09", o, win[(J)+12]);                                    \
    FMAW("3DA541FF", o, win[(J)+13]);                                    \
    FMAW("3D6006BB", o, win[(J)+14]);                                    \
    FMAW("3D07E108", o, win[(J)+15]);                                    \
    FMAW("3C937EED", o, win[(J)+16]);                                    \
    FMAW("3C0F4500", o, win[(J)+17]);                                    \
    FMAW("3B790EE0", o, win[(J)+18]);                                    \
    FMAW("3AC1B722", o, win[(J)+19]);                                    \
    FMAW("3A06D334", o, win[(J)+20]);                                    \
} while (0)

// Output-stationary 21-tap conv, 16 outputs, window of 36 register-resident
// values, 336 FFMA-imm. Accumulation order (k ascending) matches prior rounds.
#define CONV16I(LOADEXPR, OUTSTMT)                                       \
    {                                                                    \
        float win[36];                                                   \
        _Pragma("unroll") for (int m = 0; m < 36; m++) win[m] = (LOADEXPR); \
        float o[16];                                                     \
        _Pragma("unroll") for (int j = 0; j < 16; j++) o[j] = 0.0f;      \
        TAPS(o[0], 0);   TAPS(o[1], 1);   TAPS(o[2], 2);   TAPS(o[3], 3);   \
        TAPS(o[4], 4);   TAPS(o[5], 5);   TAPS(o[6], 6);   TAPS(o[7], 7);   \
        TAPS(o[8], 8);   TAPS(o[9], 9);   TAPS(o[10], 10); TAPS(o[11], 11); \
        TAPS(o[12], 12); TAPS(o[13], 13); TAPS(o[14], 14); TAPS(o[15], 15); \
        _Pragma("unroll") for (int j = 0; j < 16; j++) { OUTSTMT; }      \
    }

// ---------------------------------------------------------------------------
// Rotate points + trilinear scatter (champion form: one 256-point chunk per
// block, red.v2.f32 fast path). LTS-lane-floor bound, ~50us.
// ---------------------------------------------------------------------------
__global__ void k_scatter(const float* __restrict__ pc,
                          const float* __restrict__ rot) {
    int t = threadIdx.x;
    int b = blockIdx.x >> 8;                     // 256 blocks per batch
    __shared__ float R[9];
    __shared__ float sp[768];                    // 256 points * 3
    if (t < 9) R[t] = rot[b * 9 + t];
    const float* pblk = pc + (size_t)blockIdx.x * 768;
    sp[t]       = pblk[t];
    sp[t + 256] = pblk[t + 256];
    sp[t + 512] = pblk[t + 512];
    __syncthreads();

    float px = sp[t * 3 + 0];
    float py = sp[t * 3 + 1];
    float pz = sp[t * 3 + 2];

    float tx = fmaf(px, R[0], fmaf(py, R[1], pz * R[2]));
    float ty = fmaf(px, R[3], fmaf(py, R[4], pz * R[5]));
    float tz = fmaf(px, R[6], fmaf(py, R[7], pz * R[8]));

    float gx = (tx + 0.5f) * 63.0f;
    float gy = (ty + 0.5f) * 63.0f;
    float gz = (tz + 0.5f) * 63.0f;
    float fx = floorf(gx), fy = floorf(gy), fz = floorf(gz);
    int ix = (int)fx, iy = (int)fy, iz = (int)fz;
    float ax = gx - fx, ay = gy - fy, az = gz - fz;

    float wx0 = 1.0f - ax, wx1 = ax;
    float wy[2] = {1.0f - ay, ay};
    float wz[2] = {1.0f - az, az};

    float* base = g_vox + (size_t)b * S3;
    bool evenfast = ((ix & 1) == 0) && ((unsigned)ix <= 62u);
#pragma unroll
    for (int c = 0; c < 4; c++) {
        int dy = c & 1, dz = c >> 1;
        int Y = iy + dy, Z = iz + dz;
        if ((unsigned)Y >= S || (unsigned)Z >= S) continue;
        float wr = wy[dy] * wz[dz];
        float* row = base + Z * S2 + Y * S;
        if (evenfast) {
            asm volatile("red.global.add.v2.f32 [%0], {%1,%2};"
                         :: "l"(row + ix), "f"(wr * wx0), "f"(wr * wx1)
                         : "memory");
        } else {
            if ((unsigned)ix < S)       atomicAdd(row + ix,     wr * wx0);
            if ((unsigned)(ix + 1) < S) atomicAdd(row + ix + 1, wr * wx1);
        }
    }
}

// ---------------------------------------------------------------------------
// Fused conv along X then Y (clip raw voxels on load). One block per (b,z).
// Output layout transposed: g_tmp[b][y][z][x] so convz reads contiguously.
// ---------------------------------------------------------------------------
__global__ void __launch_bounds__(256) k_convxy() {
    int bz = blockIdx.x;
    int b = bz >> 6, z = bz & 63;
    const float* src = g_vox + (size_t)bz * S2;
    float* dstb = g_tmp + (size_t)b * S3 + z * S;      // + y*S2 + x
    __shared__ float A[S * 85];      // [y][x+10], x pads zeroed
    __shared__ float B[84 * 65];     // [y+10][x], y pads zeroed
    int t = threadIdx.x;

    for (int i = t; i < S * 85; i += 256) A[i] = 0.0f;
    for (int i = t; i < 10 * 65; i += 256) { B[i] = 0.0f; B[74 * 65 + i] = 0.0f; }
    __syncthreads();
    for (int i = t; i < S2; i += 256) {
        int y = i >> 6, x = i & 63;
        float v = src[i];
        A[y * 85 + x + 10] = fminf(fmaxf(v, 0.0f), 1.0f);
    }
    __syncthreads();

    {   // conv X: warp = 32 consecutive y (stride 85 -> conflict-free)
        int y  = t & 63;
        int x0 = (t >> 6) * 16;
        const float* row = A + y * 85 + x0;
        float* brow = B + (y + 10) * 65 + x0;
        CONV16I(row[m], brow[j] = o[j]);
    }
    __syncthreads();

    {   // conv Y: warp = 32 consecutive x (stride 1 -> conflict-free)
        int x  = t & 63;
        int y0 = (t >> 6) * 16;
        const float* col = B + y0 * 65 + x;
        float* d = dstb + (size_t)y0 * S2 + x;          // [b][y][z][x]
        CONV16I(col[m * 65], d[(size_t)j * S2] = o[j]);
    }
}

// ---------------------------------------------------------------------------
// Conv along Z + scale + clip + DRC product + flip. One block per (b,y).
// Reads g_tmp[b][y][:][:] contiguously (16KB). Re-zeroes its g_vox chunk.
// ---------------------------------------------------------------------------
__global__ void __launch_bounds__(256) k_convz(const float* __restrict__ scale,
                                               float* __restrict__ out) {
    int by = blockIdx.x;
    int b = by >> 6, y = by & 63;
    const float* src = g_tmp + (size_t)by * S2;     // [z][x] contiguous
    __shared__ float Bz[84 * 65];    // [z+10][x]
    __shared__ float part[4][S];
    int t = threadIdx.x;

    for (int i = t; i < 10 * 65; i += 256) { Bz[i] = 0.0f; Bz[74 * 65 + i] = 0.0f; }
    for (int i = t; i < S2; i += 256) {
        int z = i >> 6, x = i & 63;
        Bz[(z + 10) * 65 + x] = src[i];
    }
    {   // re-zero this block's chunk of the voxel grid for next replay
        float4* vz = reinterpret_cast<float4*>(g_vox + (size_t)by * S2);
#pragma unroll
        for (int i = 0; i < 4; i++)
            vz[t + 256 * i] = make_float4(0.f, 0.f, 0.f, 0.f);
    }
    __syncthreads();

    float sc = scale[b];
    int x  = t & 63;
    int z0 = (t >> 6) * 16;
    const float* col = Bz + z0 * 65 + x;

    float T = 1.0f;
    CONV16I(col[m * 65],
            { float a = fminf(fmaxf(o[j] * sc, 0.0f), 1.0f); T *= (1.0f - a); });

    part[t >> 6][x] = T;
    __syncthreads();
    if (t < 64) {
        float Tt = part[0][x] * part[1][x] * part[2][x] * part[3][x];
        out[(size_t)b * S2 + (63 - y) * S + x] = 1.0f - Tt;
    }
}

// ---------------------------------------------------------------------------
extern "C" void kernel_launch(void* const* d_in, const int* in_sizes, int n_in,
                              void* d_out, int out_size) {
    const float* pc    = (const float*)d_in[0];
    const float* rot   = (const float*)d_in[1];
    const float* scale = (const float*)d_in[2];
    float* out = (float*)d_out;

    k_scatter<<<NB * NPTS / 256, 256>>>(pc, rot);
    k_convxy<<<NB * S, 256>>>();
    k_convz<<<NB * S, 256>>>(scale, out);
}